// round 5
// baseline (speedup 1.0000x reference)
#include <cuda_runtime.h>
#include <cstdint>
#include <cstddef>

#define LORA_SCALING 4.0f   // alpha/rank = 32/8

// ---------------------------------------------------------------------------
// Static scratch: tf32-pre-rounded, k-permuted operands
// ---------------------------------------------------------------------------
#define MAX_M 8192
#define MAX_K 1600
#define MAX_N 4800
__device__ float g_xc[MAX_M * MAX_K];          // x, tf32(RNA), k-perm per 32-tile
__device__ float g_wc[(size_t)MAX_K * MAX_N];  // W, tf32(RNA), rows k-perm per 32-tile
__device__ float g_tp[MAX_M * 32];             // T=(x@A)*s, tf32, padded 32, k-perm
__device__ float g_bp[32 * MAX_N];             // loraB padded to 32 rows, tf32, k-perm

__device__ __forceinline__ uint32_t f2tf32(float f) {
    uint32_t u;
    asm("cvt.rna.tf32.f32 %0, %1;" : "=r"(u) : "f"(f));
    return u;
}
// permutation of k within a 32-wide tile:
// orig k = ks*8 + half*4 + t4  ->  pos = t4*8 + ks*2 + half
__host__ __device__ __forceinline__ int kperm(int k) {
    return (k & 3) * 8 + ((k >> 3) << 1) + ((k >> 2) & 1);
}

// ---------------------------------------------------------------------------
// Kernel 1 (fused): per row, T[row][32] = pad(perm(tf32((x@A)*s)));
// also writes xc[row][k-permuted] = tf32(x[row][k]).  One warp per row.
// ---------------------------------------------------------------------------
template <int R>
__global__ void lora_xa_fused(const float* __restrict__ x,
                              const float* __restrict__ A,
                              float* __restrict__ Tp,
                              float* __restrict__ xc,
                              int M, int K, float scale) {
    extern __shared__ float As[];  // [R][K]
    int tid = threadIdx.x;
    for (int i = tid; i < K * R; i += blockDim.x) {
        int k = i / R, r = i - k * R;
        As[r * K + k] = A[i];
    }
    __syncthreads();

    int w = tid >> 5, lane = tid & 31;
    int row = blockIdx.x * (blockDim.x >> 5) + w;
    if (row >= M) return;

    const float* xr = x + (size_t)row * K;
    float* xcr = xc + (size_t)row * K;
    const int kp = kperm(lane);     // k & 31 == lane always

    float acc[R];
#pragma unroll
    for (int r = 0; r < R; r++) acc[r] = 0.f;

    for (int k = lane; k < K; k += 32) {
        float xv = xr[k];
        xcr[(k & ~31) + kp] = __uint_as_float(f2tf32(xv));
#pragma unroll
        for (int r = 0; r < R; r++) acc[r] += xv * As[r * K + k];
    }
#pragma unroll
    for (int r = 0; r < R; r++)
#pragma unroll
        for (int off = 16; off; off >>= 1)
            acc[r] += __shfl_down_sync(0xffffffffu, acc[r], off);
    if (lane == 0) {
#pragma unroll
        for (int p = 0; p < 32; p++) Tp[(size_t)row * 32 + p] = 0.f;
#pragma unroll
        for (int r = 0; r < R; r++)
            Tp[(size_t)row * 32 + kperm(r)] =
                __uint_as_float(f2tf32(acc[r] * scale));
    }
}

__global__ void lora_xa_fused_gen(const float* __restrict__ x,
                                  const float* __restrict__ A,
                                  float* __restrict__ Tp,
                                  float* __restrict__ xc,
                                  int M, int K, int R, float scale) {
    extern __shared__ float As[];
    int tid = threadIdx.x;
    for (int i = tid; i < K * R; i += blockDim.x) {
        int k = i / R, r = i - k * R;
        As[r * K + k] = A[i];
    }
    __syncthreads();
    int w = tid >> 5, lane = tid & 31;
    int row = blockIdx.x * (blockDim.x >> 5) + w;
    if (row >= M) return;
    const float* xr = x + (size_t)row * K;
    float* xcr = xc + (size_t)row * K;
    const int kp = kperm(lane);
    float acc[32];
    for (int r = 0; r < 32; r++) acc[r] = 0.f;
    for (int k = lane; k < K; k += 32) {
        float xv = xr[k];
        xcr[(k & ~31) + kp] = __uint_as_float(f2tf32(xv));
        for (int r = 0; r < R; r++) acc[r] += xv * As[r * K + k];
    }
    for (int r = 0; r < 32; r++) {
        for (int off = 16; off; off >>= 1)
            acc[r] += __shfl_down_sync(0xffffffffu, acc[r], off);
    }
    if (lane == 0) {
        for (int p = 0; p < 32; p++) Tp[(size_t)row * 32 + p] = 0.f;
        for (int r = 0; r < R && r < 32; r++)
            Tp[(size_t)row * 32 + kperm(r)] =
                __uint_as_float(f2tf32(acc[r] * scale));
    }
}

// ---------------------------------------------------------------------------
// Kernel 2: wc[tile32(k) + kperm(k%32)][n] = tf32(W[k][n])   (float4, coalesced)
// ---------------------------------------------------------------------------
__global__ void cvt_w_perm(const float* __restrict__ W, float* __restrict__ wc,
                           int K, int N) {
    int i = blockIdx.x * blockDim.x + threadIdx.x;   // over K*N/4
    int n4 = N >> 2;
    if (i >= K * n4) return;
    int k = i / n4, c4 = i - k * n4;
    int kd = (k & ~31) + kperm(k & 31);
    float4 v = reinterpret_cast<const float4*>(W + (size_t)k * N)[c4];
    v.x = __uint_as_float(f2tf32(v.x));
    v.y = __uint_as_float(f2tf32(v.y));
    v.z = __uint_as_float(f2tf32(v.z));
    v.w = __uint_as_float(f2tf32(v.w));
    reinterpret_cast<float4*>(wc + (size_t)kd * N)[c4] = v;
}

// ---------------------------------------------------------------------------
// Kernel 3: Bp[32][N]: row kperm(r) = tf32(loraB[r][n]), zero elsewhere
// ---------------------------------------------------------------------------
__global__ void bpad_perm(const float* __restrict__ lB, float* __restrict__ Bp,
                          int N, int R) {
    int n = blockIdx.x * blockDim.x + threadIdx.x;
    if (n >= N) return;
#pragma unroll
    for (int p = 0; p < 32; p++) Bp[(size_t)p * N + n] = 0.f;
    for (int r = 0; r < R && r < 32; r++)
        Bp[(size_t)kperm(r) * N + n] =
            __uint_as_float(f2tf32(lB[(size_t)r * N + n]));
}

// ---------------------------------------------------------------------------
// Kernel 4: GEMM.  out = xc@wc (+ Tp@Bp pseudo-tile) + bias
// TF32 mma.sync m16n8k8, BM=128 BN=128 BK=32, warps 2(m)x4(n),
// A frags via LDS.128 (k-perm), B scalar LDS with XOR-chunk swizzle.
// ---------------------------------------------------------------------------
#define BM 128
#define BN 128
#define BK 32
#define ASTRIDE 36
#define BSTRIDE 136

__device__ __forceinline__ void mma_tf32(float* c, const uint32_t* a, const uint32_t* b) {
    asm volatile(
        "mma.sync.aligned.m16n8k8.row.col.f32.tf32.tf32.f32 "
        "{%0,%1,%2,%3}, {%4,%5,%6,%7}, {%8,%9}, {%0,%1,%2,%3};"
        : "+f"(c[0]), "+f"(c[1]), "+f"(c[2]), "+f"(c[3])
        : "r"(a[0]), "r"(a[1]), "r"(a[2]), "r"(a[3]), "r"(b[0]), "r"(b[1]));
}
__device__ __forceinline__ void cp_async16(uint32_t dst, const void* src, int src_bytes) {
    asm volatile("cp.async.cg.shared.global [%0], [%1], 16, %2;\n"
                 :: "r"(dst), "l"(src), "r"(src_bytes));
}

__global__ __launch_bounds__(256, 2)
void lora_gemm_kernel(const float* __restrict__ xc, const float* __restrict__ wc,
                      const float* __restrict__ bias, const float* __restrict__ Tp,
                      const float* __restrict__ Bp, float* __restrict__ out,
                      int M, int N, int K) {
    extern __shared__ float smem[];
    float* As = smem;                          // [2][BM][ASTRIDE]
    float* Bs = smem + 2 * BM * ASTRIDE;       // [2][BK][BSTRIDE]

    const int tid = threadIdx.x;
    const int m0 = blockIdx.y * BM;
    const int n0 = blockIdx.x * BN;
    const int KT = K / BK;
    const int NT = KT + 1;        // + LoRA pseudo tile

    int ar[4], ac[4], bk_[4], bc[4];
#pragma unroll
    for (int i = 0; i < 4; i++) {
        int idx = tid + i * 256;
        ar[i] = idx >> 3;  ac[i] = (idx & 7) * 4;
        bk_[i] = idx >> 5; bc[i] = (idx & 31) * 4;
    }

    auto prefetch = [&](int kt, int buf) {
        float* Asb = As + buf * (BM * ASTRIDE);
        float* Bsb = Bs + buf * (BK * BSTRIDE);
        bool pseudo = (kt == KT);
#pragma unroll
        for (int i = 0; i < 4; i++) {
            uint32_t dst = (uint32_t)__cvta_generic_to_shared(Asb + ar[i] * ASTRIDE + ac[i]);
            int grow = m0 + ar[i];
            const float* src = pseudo ? (Tp + (size_t)grow * 32 + ac[i])
                                      : (xc + (size_t)grow * K + kt * BK + ac[i]);
            cp_async16(dst, src, (grow < M) ? 16 : 0);
        }
#pragma unroll
        for (int i = 0; i < 4; i++) {
            // XOR-chunk swizzle on B rows: chunk' = chunk ^ ((row>>3)<<1)
            int swc = ((bc[i] >> 2) ^ (((bk_[i] >> 3) & 3) << 1)) << 2;
            uint32_t dst = (uint32_t)__cvta_generic_to_shared(Bsb + bk_[i] * BSTRIDE + swc);
            int gcol = n0 + bc[i];
            bool colok = (gcol + 4 <= N);
            const float* src = pseudo ? (Bp + (size_t)bk_[i] * N + gcol)
                                      : (wc + (size_t)(kt * BK + bk_[i]) * N + gcol);
            cp_async16(dst, src, colok ? 16 : 0);
        }
        asm volatile("cp.async.commit_group;\n" ::: "memory");
    };

    // Warp layout: 8 warps = 2(m) x 4(n); warp tile 64 x 32
    const int w = tid >> 5, lane = tid & 31;
    const int wm = (w >> 2) * 64;
    const int wn = (w & 3) * 32;
    const int g = lane >> 2, t4 = lane & 3;

    // Precomputed swizzled B column offsets (per ni), hoisted out of k-loop.
    int scol[4];
#pragma unroll
    for (int ni = 0; ni < 4; ni++) {
        int cfull = wn + ni * 8 + g;
        scol[ni] = ((((cfull >> 2) ^ (t4 << 1)) << 2) | (cfull & 3));
    }

    float acc[4][4][4];
#pragma unroll
    for (int mi = 0; mi < 4; mi++)
#pragma unroll
        for (int ni = 0; ni < 4; ni++)
#pragma unroll
            for (int e = 0; e < 4; e++) acc[mi][ni][e] = 0.f;

    prefetch(0, 0);
    int buf = 0;
    for (int kt = 0; kt < NT; kt++) {
        asm volatile("cp.async.wait_group 0;\n" ::: "memory");
        __syncthreads();
        if (kt + 1 < NT) prefetch(kt + 1, buf ^ 1);

        const uint4* A4 = reinterpret_cast<const uint4*>(As + buf * (BM * ASTRIDE));
        const uint32_t* Bu = reinterpret_cast<const uint32_t*>(Bs + buf * (BK * BSTRIDE));

#pragma unroll
        for (int ks2 = 0; ks2 < 2; ks2++) {
            uint4 va[4][2];
#pragma unroll
            for (int mi = 0; mi < 4; mi++) {
                int r0 = wm + mi * 16 + g;
                va[mi][0] = A4[(r0 * ASTRIDE + t4 * 8 + ks2 * 4) >> 2];
                va[mi][1] = A4[((r0 + 8) * ASTRIDE + t4 * 8 + ks2 * 4) >> 2];
            }
#pragma unroll
            for (int sub = 0; sub < 2; sub++) {
                const int ks = ks2 * 2 + sub;
                const int p0 = t4 * 8 + ks * 2;     // permuted row: orig k = ks*8+t4
                uint32_t bfr[4][2];
#pragma unroll
                for (int ni = 0; ni < 4; ni++) {
                    bfr[ni][0] = Bu[p0 * BSTRIDE + scol[ni]];
                    bfr[ni][1] = Bu[(p0 + 1) * BSTRIDE + scol[ni]];
                }
#pragma unroll
                for (int mi = 0; mi < 4; mi++) {
                    uint32_t afr[4];
                    if (sub == 0) {
                        afr[0] = va[mi][0].x; afr[1] = va[mi][1].x;
                        afr[2] = va[mi][0].y; afr[3] = va[mi][1].y;
                    } else {
                        afr[0] = va[mi][0].z; afr[1] = va[mi][1].z;
                        afr[2] = va[mi][0].w; afr[3] = va[mi][1].w;
                    }
#pragma unroll
                    for (int ni = 0; ni < 4; ni++)
                        mma_tf32(acc[mi][ni], afr, bfr[ni]);
                }
            }
        }
        buf ^= 1;
    }

    // Epilogue: bias + float2 stores
#pragma unroll
    for (int mi = 0; mi < 4; mi++) {
        int r0 = m0 + wm + mi * 16 + g;
        int r1 = r0 + 8;
#pragma unroll
        for (int ni = 0; ni < 4; ni++) {
            int c = n0 + wn + ni * 8 + 2 * t4;
            if (c + 1 < N) {
                float bv0 = __ldg(bias + c);
                float bv1 = __ldg(bias + c + 1);
                if (r0 < M) {
                    float2 v = make_float2(acc[mi][ni][0] + bv0, acc[mi][ni][1] + bv1);
                    *reinterpret_cast<float2*>(out + (size_t)r0 * N + c) = v;
                }
                if (r1 < M) {
                    float2 v = make_float2(acc[mi][ni][2] + bv0, acc[mi][ni][3] + bv1);
                    *reinterpret_cast<float2*>(out + (size_t)r1 * N + c) = v;
                }
            }
        }
    }
}

// ---------------------------------------------------------------------------
extern "C" void kernel_launch(void* const* d_in, const int* in_sizes, int n_in,
                              void* d_out, int out_size) {
    const float* x  = (const float*)d_in[0];
    const float* W  = (const float*)d_in[1];
    const float* b  = (const float*)d_in[2];
    const float* lA = (const float*)d_in[3];
    const float* lB = (const float*)d_in[4];
    float* out = (float*)d_out;

    const int Dout = in_sizes[2];
    const int Din  = in_sizes[1] / Dout;
    const int R    = in_sizes[3] / Din;
    const int M    = in_sizes[0] / Din;
    const int N    = Dout;
    const int K    = Din;

    float *xc, *wc, *tp, *bp;
    cudaGetSymbolAddress((void**)&xc, g_xc);
    cudaGetSymbolAddress((void**)&wc, g_wc);
    cudaGetSymbolAddress((void**)&tp, g_tp);
    cudaGetSymbolAddress((void**)&bp, g_bp);

    // 1) fused: T=(x@A)*s (tf32, perm, pad32) and xc = tf32(x) k-permuted
    {
        const int threads = 512;                 // 16 rows/block
        const int grid = (M + 15) / 16;
        const size_t smem = (size_t)R * K * sizeof(float);
        if (R == 8) {
            cudaFuncSetAttribute(lora_xa_fused<8>, cudaFuncAttributeMaxDynamicSharedMemorySize, (int)smem);
            lora_xa_fused<8><<<grid, threads, smem>>>(x, lA, tp, xc, M, K, LORA_SCALING);
        } else if (R == 16) {
            cudaFuncSetAttribute(lora_xa_fused<16>, cudaFuncAttributeMaxDynamicSharedMemorySize, (int)smem);
            lora_xa_fused<16><<<grid, threads, smem>>>(x, lA, tp, xc, M, K, LORA_SCALING);
        } else if (R == 4) {
            cudaFuncSetAttribute(lora_xa_fused<4>, cudaFuncAttributeMaxDynamicSharedMemorySize, (int)smem);
            lora_xa_fused<4><<<grid, threads, smem>>>(x, lA, tp, xc, M, K, LORA_SCALING);
        } else {
            cudaFuncSetAttribute(lora_xa_fused_gen, cudaFuncAttributeMaxDynamicSharedMemorySize, (int)smem);
            lora_xa_fused_gen<<<grid, threads, smem>>>(x, lA, tp, xc, M, K, R, LORA_SCALING);
        }
    }
    // 2) wc = tf32(W), rows k-permuted
    {
        int total = K * (N >> 2);
        cvt_w_perm<<<(total + 255) / 256, 256>>>(W, wc, K, N);
    }
    // 3) Bp = padded/permuted tf32(loraB)
    bpad_perm<<<(N + 255) / 256, 256>>>(lB, bp, N, R);

    // 4) GEMM
    {
        const int smem = (2 * BM * ASTRIDE + 2 * BK * BSTRIDE) * (int)sizeof(float); // 71680
        cudaFuncSetAttribute(lora_gemm_kernel, cudaFuncAttributeMaxDynamicSharedMemorySize, smem);
        dim3 grid((N + BN - 1) / BN, (M + BM - 1) / BM);
        lora_gemm_kernel<<<grid, 256, smem>>>(xc, wc, b, tp, bp, out, M, N, K);
    }
}